// round 4
// baseline (speedup 1.0000x reference)
#include <cuda_runtime.h>
#include <stdint.h>

// Problem constants (fixed by setup_inputs)
#define B   16
#define N   8192
#define P   1024
#define C   256
#define K   64
#define OUTC (3 + C)   // 259

// Scratch for ball-query indices: [B, P, K] int32 = 4 MB (static device array: allowed)
__device__ int g_idx[B * P * K];

// ---------------------------------------------------------------------------
// Kernel 1: ball query (warp per center) + grouped_xyz channels [0..2]
// Arithmetic variant V8:
//   squares  : separately rounded muls
//   ssq tree : (x^2 + z^2) + y^2     <- XLA multi-row warp-shuffle reduce tree
//   dot      : fma(cz,z, fma(cy,y, rn(cx*x)))   <- cuBLAS SIMT ascending-k chain
//   d2       : (cc + xx) - 2*dot     (2*dot exact)
//   in       : d2 < (float)(0.3*0.3)
// Selection: first K indices in ascending point order; empty slots filled
// with first found index (0 if none).
// ---------------------------------------------------------------------------
__global__ __launch_bounds__(256) void ball_query_kernel(
    const float* __restrict__ xyz,      // [B, N, 3]
    const float* __restrict__ new_xyz,  // [B, P, 3]
    float* __restrict__ out)            // [B, OUTC, P, K]
{
    const float R2 = (float)(0.3 * 0.3);

    __shared__ int s_idx[8][K];   // 8 warps per block

    int lane = threadIdx.x & 31;
    int wid  = threadIdx.x >> 5;
    int cid  = blockIdx.x * 8 + wid;          // center id in [0, B*P)
    int b    = cid >> 10;                     // /1024
    int p    = cid & 1023;

    const float* ctr = new_xyz + ((size_t)b * P + p) * 3;
    float cx = ctr[0], cy = ctr[1], cz = ctr[2];
    // (cx^2 + cz^2) + cy^2, all separately rounded
    float cc = __fadd_rn(__fadd_rn(__fmul_rn(cx, cx), __fmul_rn(cz, cz)),
                         __fmul_rn(cy, cy));

    const float* pts = xyz + (size_t)b * N * 3;

    int count = 0;
    unsigned lmask = (1u << lane) - 1u;
    for (int base = 0; base < N; base += 32) {
        int n = base + lane;                   // N % 32 == 0: always valid
        const float* q = pts + (size_t)n * 3;
        float x = q[0], y = q[1], z = q[2];
        // (x^2 + z^2) + y^2, all separately rounded (shuffle-tree order)
        float xx  = __fadd_rn(__fadd_rn(__fmul_rn(x, x), __fmul_rn(z, z)),
                              __fmul_rn(y, y));
        // ascending-k single-accumulator fma chain (cublas SIMT)
        float dot = __fmaf_rn(cz, z, __fmaf_rn(cy, y, __fmul_rn(cx, x)));
        float d2  = __fsub_rn(__fadd_rn(cc, xx), __fmul_rn(2.0f, dot));
        bool in = d2 < R2;
        unsigned m = __ballot_sync(0xffffffffu, in);
        int pos = count + __popc(m & lmask);
        if (in && pos < K) s_idx[wid][pos] = n;
        count += __popc(m);
        if (count >= K) break;
    }
    if (count > K) count = K;
    __syncwarp();

    int first = (count == 0) ? 0 : s_idx[wid][0];
    for (int k = count + lane; k < K; k += 32) s_idx[wid][k] = first;
    __syncwarp();

    // Emit idx + grouped_xyz channels (lane handles k = lane, lane+32)
    int*   gidx = g_idx + ((size_t)b * P + p) * K;
    size_t obase = (((size_t)b * OUTC) * P + p) * K;   // channel 0 offset
    #pragma unroll
    for (int t = 0; t < 2; t++) {
        int k = lane + t * 32;
        int n = s_idx[wid][k];
        gidx[k] = n;
        const float* q = pts + (size_t)n * 3;
        float gx = __fdiv_rn(__fsub_rn(q[0], cx), 0.3f);
        float gy = __fdiv_rn(__fsub_rn(q[1], cy), 0.3f);
        float gz = __fdiv_rn(__fsub_rn(q[2], cz), 0.3f);
        out[obase + 0 * (size_t)P * K + k] = gx;
        out[obase + 1 * (size_t)P * K + k] = gy;
        out[obase + 2 * (size_t)P * K + k] = gz;
    }
}

// ---------------------------------------------------------------------------
// Kernel 2: feature grouping. One block per (b, c): stage the 32 KB feature
// row in shared memory, then gather P*K = 65536 values via LDS and stream
// them out with float4 stores (write-bound).
// ---------------------------------------------------------------------------
__global__ __launch_bounds__(256) void group_feat_kernel(
    const float* __restrict__ feat,   // [B, C, N]
    float* __restrict__ out)          // [B, OUTC, P, K]
{
    __shared__ float row[N];          // 32 KB

    int b = blockIdx.x >> 8;          // / C
    int c = blockIdx.x & (C - 1);

    const float4* src = (const float4*)(feat + ((size_t)b * C + c) * N);
    #pragma unroll
    for (int i = threadIdx.x; i < N / 4; i += 256)
        ((float4*)row)[i] = src[i];
    __syncthreads();

    const int4* idx4 = (const int4*)g_idx + (size_t)b * (P * K / 4);
    float4* dst = (float4*)(out + (((size_t)b * OUTC + 3 + c) * P) * K);

    #pragma unroll 4
    for (int i = threadIdx.x; i < P * K / 4; i += 256) {
        int4 v = idx4[i];
        float4 o;
        o.x = row[v.x];
        o.y = row[v.y];
        o.z = row[v.z];
        o.w = row[v.w];
        dst[i] = o;
    }
}

extern "C" void kernel_launch(void* const* d_in, const int* in_sizes, int n_in,
                              void* d_out, int out_size)
{
    (void)in_sizes; (void)n_in; (void)out_size;
    const float* xyz     = (const float*)d_in[0];   // [16, 8192, 3]
    const float* new_xyz = (const float*)d_in[1];   // [16, 1024, 3]
    const float* feat    = (const float*)d_in[2];   // [16, 256, 8192]
    float* out = (float*)d_out;                     // [16, 259, 1024, 64]

    ball_query_kernel<<<(B * P) / 8, 256>>>(xyz, new_xyz, out);
    group_feat_kernel<<<B * C, 256>>>(feat, out);
}

// round 5
// speedup vs baseline: 1.2624x; 1.2624x over previous
#include <cuda_runtime.h>
#include <stdint.h>

#define B    16
#define N    8192
#define P    1024
#define C    256
#define K    64
#define OUTC (3 + C)   // 259
#define CPB  4         // channels per block in group_feat

// Scratch for ball-query indices: [B, P, K] int32 = 4 MB
__device__ int g_idx[B * P * K];

// ---------------------------------------------------------------------------
// Kernel 1: ball query (warp per center) + grouped_xyz channels [0..2].
// Arithmetic (validated in R4, bit-matches reference):
//   ssq tree : (x^2 + z^2) + y^2, separately-rounded muls
//   dot      : fma(cz,z, fma(cy,y, rn(cx*x)))
//   d2       : (cc + xx) - 2*dot
// Selection: first K ascending indices with d2 < r^2; empty slots filled
// with first found index (0 if none).
// 64 points per iteration (2 ballots) to halve the serial latency chain.
// ---------------------------------------------------------------------------
__global__ __launch_bounds__(256) void ball_query_kernel(
    const float* __restrict__ xyz,      // [B, N, 3]
    const float* __restrict__ new_xyz,  // [B, P, 3]
    float* __restrict__ out)            // [B, OUTC, P, K]
{
    const float R2 = (float)(0.3 * 0.3);

    __shared__ int s_idx[8][K];

    int lane = threadIdx.x & 31;
    int wid  = threadIdx.x >> 5;
    int cid  = blockIdx.x * 8 + wid;
    int b    = cid >> 10;
    int p    = cid & 1023;

    const float* ctr = new_xyz + ((size_t)b * P + p) * 3;
    float cx = ctr[0], cy = ctr[1], cz = ctr[2];
    float cc = __fadd_rn(__fadd_rn(__fmul_rn(cx, cx), __fmul_rn(cz, cz)),
                         __fmul_rn(cy, cy));

    const float* pts = xyz + (size_t)b * N * 3;

    int count = 0;
    unsigned lmask = (1u << lane) - 1u;
    for (int base = 0; base < N; base += 64) {
        int n0 = base + lane;
        int n1 = base + 32 + lane;
        const float* q0 = pts + (size_t)n0 * 3;
        const float* q1 = pts + (size_t)n1 * 3;
        // issue all 6 loads up front (MLP)
        float x0 = q0[0], y0 = q0[1], z0 = q0[2];
        float x1 = q1[0], y1 = q1[1], z1 = q1[2];

        float xx0  = __fadd_rn(__fadd_rn(__fmul_rn(x0, x0), __fmul_rn(z0, z0)),
                               __fmul_rn(y0, y0));
        float dot0 = __fmaf_rn(cz, z0, __fmaf_rn(cy, y0, __fmul_rn(cx, x0)));
        float d20  = __fsub_rn(__fadd_rn(cc, xx0), __fmul_rn(2.0f, dot0));
        float xx1  = __fadd_rn(__fadd_rn(__fmul_rn(x1, x1), __fmul_rn(z1, z1)),
                               __fmul_rn(y1, y1));
        float dot1 = __fmaf_rn(cz, z1, __fmaf_rn(cy, y1, __fmul_rn(cx, x1)));
        float d21  = __fsub_rn(__fadd_rn(cc, xx1), __fmul_rn(2.0f, dot1));

        bool in0 = d20 < R2;
        bool in1 = d21 < R2;
        unsigned m0 = __ballot_sync(0xffffffffu, in0);
        unsigned m1 = __ballot_sync(0xffffffffu, in1);
        int c0 = __popc(m0);
        int pos0 = count + __popc(m0 & lmask);
        int pos1 = count + c0 + __popc(m1 & lmask);
        if (in0 && pos0 < K) s_idx[wid][pos0] = n0;
        if (in1 && pos1 < K) s_idx[wid][pos1] = n1;
        count += c0 + __popc(m1);
        if (count >= K) break;
    }
    if (count > K) count = K;
    __syncwarp();

    int first = (count == 0) ? 0 : s_idx[wid][0];
    for (int k = count + lane; k < K; k += 32) s_idx[wid][k] = first;
    __syncwarp();

    int*   gidx = g_idx + ((size_t)b * P + p) * K;
    size_t obase = (((size_t)b * OUTC) * P + p) * K;
    #pragma unroll
    for (int t = 0; t < 2; t++) {
        int k = lane + t * 32;
        int n = s_idx[wid][k];
        gidx[k] = n;
        const float* q = pts + (size_t)n * 3;
        float gx = __fdiv_rn(__fsub_rn(q[0], cx), 0.3f);
        float gy = __fdiv_rn(__fsub_rn(q[1], cy), 0.3f);
        float gz = __fdiv_rn(__fsub_rn(q[2], cz), 0.3f);
        out[obase + 0 * (size_t)P * K + k] = gx;
        out[obase + 1 * (size_t)P * K + k] = gy;
        out[obase + 2 * (size_t)P * K + k] = gz;
    }
}

// ---------------------------------------------------------------------------
// Kernel 2: feature grouping, 4 channels per block.
// Stage an interleaved float4 image of 4 feature rows in 128 KB dynamic smem:
//   srow[n] = { c0[n], c1[n], c2[n], c3[n] }
// Then each gathered point index needs ONE LDS.128 (serves 4 channels), and
// the idx array is read once per 4 channels instead of once per channel.
// ---------------------------------------------------------------------------
__global__ __launch_bounds__(512) void group_feat_kernel(
    const float* __restrict__ feat,   // [B, C, N]
    float* __restrict__ out)          // [B, OUTC, P, K]
{
    extern __shared__ float4 srow[];  // [N] = 128 KB

    int b  = blockIdx.x >> 6;            // / (C/CPB)
    int cq = blockIdx.x & 63;            // channel quad
    int c0 = cq * CPB;

    const float* r0 = feat + (((size_t)b * C + c0 + 0) * N);
    const float* r1 = feat + (((size_t)b * C + c0 + 1) * N);
    const float* r2 = feat + (((size_t)b * C + c0 + 2) * N);
    const float* r3 = feat + (((size_t)b * C + c0 + 3) * N);

    #pragma unroll
    for (int n = threadIdx.x; n < N; n += 512) {
        float4 v;
        v.x = r0[n]; v.y = r1[n]; v.z = r2[n]; v.w = r3[n];
        srow[n] = v;   // conflict-free STS.128 (consecutive n)
    }
    __syncthreads();

    const int4* idx4 = (const int4*)g_idx + (size_t)b * (P * K / 4);
    size_t ob = ((size_t)b * OUTC + 3 + c0) * P * K;
    float4* d0 = (float4*)(out + ob + 0 * (size_t)P * K);
    float4* d1 = (float4*)(out + ob + 1 * (size_t)P * K);
    float4* d2 = (float4*)(out + ob + 2 * (size_t)P * K);
    float4* d3 = (float4*)(out + ob + 3 * (size_t)P * K);

    #pragma unroll 4
    for (int i = threadIdx.x; i < P * K / 4; i += 512) {
        int4 v = idx4[i];
        float4 a = srow[v.x];
        float4 bb = srow[v.y];
        float4 cc = srow[v.z];
        float4 dd = srow[v.w];
        d0[i] = make_float4(a.x, bb.x, cc.x, dd.x);
        d1[i] = make_float4(a.y, bb.y, cc.y, dd.y);
        d2[i] = make_float4(a.z, bb.z, cc.z, dd.z);
        d3[i] = make_float4(a.w, bb.w, cc.w, dd.w);
    }
}

extern "C" void kernel_launch(void* const* d_in, const int* in_sizes, int n_in,
                              void* d_out, int out_size)
{
    (void)in_sizes; (void)n_in; (void)out_size;
    const float* xyz     = (const float*)d_in[0];   // [16, 8192, 3]
    const float* new_xyz = (const float*)d_in[1];   // [16, 1024, 3]
    const float* feat    = (const float*)d_in[2];   // [16, 256, 8192]
    float* out = (float*)d_out;                     // [16, 259, 1024, 64]

    const int smem_bytes = N * sizeof(float4);      // 128 KB
    cudaFuncSetAttribute(group_feat_kernel,
                         cudaFuncAttributeMaxDynamicSharedMemorySize,
                         smem_bytes);

    ball_query_kernel<<<(B * P) / 8, 256>>>(xyz, new_xyz, out);
    group_feat_kernel<<<B * (C / CPB), 512, smem_bytes>>>(feat, out);
}

// round 6
// speedup vs baseline: 1.4856x; 1.1768x over previous
#include <cuda_runtime.h>
#include <stdint.h>

#define B    16
#define N    8192
#define P    1024
#define C    256
#define K    64
#define OUTC (3 + C)   // 259
#define CPB  4         // channels per block in group_feat

// Scratch for ball-query indices: [B, P, K] int32 = 4 MB
__device__ int g_idx[B * P * K];

// ---------------------------------------------------------------------------
// Kernel 1: ball query (warp per center) + grouped_xyz channels [0..2].
// Arithmetic (validated in R4, bit-matches reference):
//   ssq tree : (x^2 + z^2) + y^2, separately-rounded muls
//   dot      : fma(cz,z, fma(cy,y, rn(cx*x)))
//   d2       : (cc + xx) - 2*dot
// Selection: first K ascending indices with d2 < r^2; empty slots filled
// with first found index (0 if none).
// ---------------------------------------------------------------------------
__global__ __launch_bounds__(256) void ball_query_kernel(
    const float* __restrict__ xyz,      // [B, N, 3]
    const float* __restrict__ new_xyz,  // [B, P, 3]
    float* __restrict__ out)            // [B, OUTC, P, K]
{
    const float R2 = (float)(0.3 * 0.3);

    __shared__ int s_idx[8][K];

    int lane = threadIdx.x & 31;
    int wid  = threadIdx.x >> 5;
    int cid  = blockIdx.x * 8 + wid;
    int b    = cid >> 10;
    int p    = cid & 1023;

    const float* ctr = new_xyz + ((size_t)b * P + p) * 3;
    float cx = ctr[0], cy = ctr[1], cz = ctr[2];
    float cc = __fadd_rn(__fadd_rn(__fmul_rn(cx, cx), __fmul_rn(cz, cz)),
                         __fmul_rn(cy, cy));

    const float* pts = xyz + (size_t)b * N * 3;

    int count = 0;
    unsigned lmask = (1u << lane) - 1u;
    for (int base = 0; base < N; base += 64) {
        int n0 = base + lane;
        int n1 = base + 32 + lane;
        const float* q0 = pts + (size_t)n0 * 3;
        const float* q1 = pts + (size_t)n1 * 3;
        // issue all 6 loads up front (MLP)
        float x0 = q0[0], y0 = q0[1], z0 = q0[2];
        float x1 = q1[0], y1 = q1[1], z1 = q1[2];

        float xx0  = __fadd_rn(__fadd_rn(__fmul_rn(x0, x0), __fmul_rn(z0, z0)),
                               __fmul_rn(y0, y0));
        float dot0 = __fmaf_rn(cz, z0, __fmaf_rn(cy, y0, __fmul_rn(cx, x0)));
        float d20  = __fsub_rn(__fadd_rn(cc, xx0), __fmul_rn(2.0f, dot0));
        float xx1  = __fadd_rn(__fadd_rn(__fmul_rn(x1, x1), __fmul_rn(z1, z1)),
                               __fmul_rn(y1, y1));
        float dot1 = __fmaf_rn(cz, z1, __fmaf_rn(cy, y1, __fmul_rn(cx, x1)));
        float d21  = __fsub_rn(__fadd_rn(cc, xx1), __fmul_rn(2.0f, dot1));

        bool in0 = d20 < R2;
        bool in1 = d21 < R2;
        unsigned m0 = __ballot_sync(0xffffffffu, in0);
        unsigned m1 = __ballot_sync(0xffffffffu, in1);
        int c0 = __popc(m0);
        int pos0 = count + __popc(m0 & lmask);
        int pos1 = count + c0 + __popc(m1 & lmask);
        if (in0 && pos0 < K) s_idx[wid][pos0] = n0;
        if (in1 && pos1 < K) s_idx[wid][pos1] = n1;
        count += c0 + __popc(m1);
        if (count >= K) break;
    }
    if (count > K) count = K;
    __syncwarp();

    int first = (count == 0) ? 0 : s_idx[wid][0];
    for (int k = count + lane; k < K; k += 32) s_idx[wid][k] = first;
    __syncwarp();

    int*   gidx = g_idx + ((size_t)b * P + p) * K;
    size_t obase = (((size_t)b * OUTC) * P + p) * K;
    #pragma unroll
    for (int t = 0; t < 2; t++) {
        int k = lane + t * 32;
        int n = s_idx[wid][k];
        gidx[k] = n;
        const float* q = pts + (size_t)n * 3;
        float gx = __fdiv_rn(__fsub_rn(q[0], cx), 0.3f);
        float gy = __fdiv_rn(__fsub_rn(q[1], cy), 0.3f);
        float gz = __fdiv_rn(__fsub_rn(q[2], cz), 0.3f);
        out[obase + 0 * (size_t)P * K + k] = gx;
        out[obase + 1 * (size_t)P * K + k] = gy;
        out[obase + 2 * (size_t)P * K + k] = gz;
    }
}

// ---------------------------------------------------------------------------
// Kernel 2: feature grouping, 4 channels per block, 1024 threads.
// Stage an interleaved float4 image of 4 feature rows in 128 KB dynamic smem:
//   srow[n] = { c0[n], c1[n], c2[n], c3[n] }
// One LDS.128 per gathered point serves 4 output channels; idx is read once
// per 4 channels.
// ---------------------------------------------------------------------------
__global__ __launch_bounds__(1024, 1) void group_feat_kernel(
    const float* __restrict__ feat,   // [B, C, N]
    float* __restrict__ out)          // [B, OUTC, P, K]
{
    extern __shared__ float4 srow[];  // [N] = 128 KB

    int b  = blockIdx.x >> 6;            // / (C/CPB)
    int cq = blockIdx.x & 63;            // channel quad
    int c0 = cq * CPB;

    const float* r0 = feat + (((size_t)b * C + c0 + 0) * N);
    const float* r1 = feat + (((size_t)b * C + c0 + 1) * N);
    const float* r2 = feat + (((size_t)b * C + c0 + 2) * N);
    const float* r3 = feat + (((size_t)b * C + c0 + 3) * N);

    #pragma unroll
    for (int n = threadIdx.x; n < N; n += 1024) {
        float4 v;
        v.x = r0[n]; v.y = r1[n]; v.z = r2[n]; v.w = r3[n];
        srow[n] = v;   // conflict-free STS.128 (consecutive n)
    }
    __syncthreads();

    const int4* idx4 = (const int4*)g_idx + (size_t)b * (P * K / 4);
    size_t ob = ((size_t)b * OUTC + 3 + c0) * P * K;
    float4* d0 = (float4*)(out + ob + 0 * (size_t)P * K);
    float4* d1 = (float4*)(out + ob + 1 * (size_t)P * K);
    float4* d2 = (float4*)(out + ob + 2 * (size_t)P * K);
    float4* d3 = (float4*)(out + ob + 3 * (size_t)P * K);

    #pragma unroll 4
    for (int i = threadIdx.x; i < P * K / 4; i += 1024) {
        int4 v = idx4[i];
        float4 a  = srow[v.x];
        float4 bb = srow[v.y];
        float4 cc = srow[v.z];
        float4 dd = srow[v.w];
        d0[i] = make_float4(a.x, bb.x, cc.x, dd.x);
        d1[i] = make_float4(a.y, bb.y, cc.y, dd.y);
        d2[i] = make_float4(a.z, bb.z, cc.z, dd.z);
        d3[i] = make_float4(a.w, bb.w, cc.w, dd.w);
    }
}

extern "C" void kernel_launch(void* const* d_in, const int* in_sizes, int n_in,
                              void* d_out, int out_size)
{
    (void)in_sizes; (void)n_in; (void)out_size;
    const float* xyz     = (const float*)d_in[0];   // [16, 8192, 3]
    const float* new_xyz = (const float*)d_in[1];   // [16, 1024, 3]
    const float* feat    = (const float*)d_in[2];   // [16, 256, 8192]
    float* out = (float*)d_out;                     // [16, 259, 1024, 64]

    const int smem_bytes = N * sizeof(float4);      // 128 KB
    cudaFuncSetAttribute(group_feat_kernel,
                         cudaFuncAttributeMaxDynamicSharedMemorySize,
                         smem_bytes);

    ball_query_kernel<<<(B * P) / 8, 256>>>(xyz, new_xyz, out);
    group_feat_kernel<<<B * (C / CPB), 1024, smem_bytes>>>(feat, out);
}

// round 7
// speedup vs baseline: 1.6270x; 1.0951x over previous
#include <cuda_runtime.h>
#include <stdint.h>

#define B    16
#define N    8192
#define P    1024
#define C    256
#define K    64
#define OUTC (3 + C)   // 259
#define CPB  4         // channels per block in group_feat

// Scratch for ball-query indices: [B, P, K] int32 = 4 MB
__device__ int g_idx[B * P * K];

// ---------------------------------------------------------------------------
// Kernel 1: ball query. 32 warps/block = 32 centers, all in the same batch.
// The whole xyz[b] (96 KB) is staged in dynamic smem; warps scan from smem
// (LDS ~29cyc vs L2 ~262cyc on the serial per-iteration dependence chain).
// Arithmetic (validated in R4, bit-matches reference):
//   ssq tree : (x^2 + z^2) + y^2, separately-rounded muls
//   dot      : fma(cz,z, fma(cy,y, rn(cx*x)))
//   d2       : (cc + xx) - 2*dot
// Selection: first K ascending indices with d2 < r^2; empty slots filled
// with first found index (0 if none).
// ---------------------------------------------------------------------------
__global__ __launch_bounds__(1024, 1) void ball_query_kernel(
    const float* __restrict__ xyz,      // [B, N, 3]
    const float* __restrict__ new_xyz,  // [B, P, 3]
    float* __restrict__ out)            // [B, OUTC, P, K]
{
    const float R2 = (float)(0.3 * 0.3);

    extern __shared__ float smem[];
    float* sxyz  = smem;                     // [3*N] = 96 KB
    int*   s_idx = (int*)(smem + 3 * N);     // [32][K] = 8 KB

    int tid  = threadIdx.x;
    int lane = tid & 31;
    int wid  = tid >> 5;                     // 0..31
    int cid  = blockIdx.x * 32 + wid;
    int b    = cid >> 10;
    int p    = cid & 1023;

    // Stage xyz[b] into smem (coalesced float4)
    const float4* src = (const float4*)(xyz + (size_t)b * N * 3);
    #pragma unroll
    for (int i = tid; i < 3 * N / 4; i += 1024)
        ((float4*)sxyz)[i] = src[i];

    const float* ctr = new_xyz + ((size_t)b * P + p) * 3;
    float cx = ctr[0], cy = ctr[1], cz = ctr[2];
    float cc = __fadd_rn(__fadd_rn(__fmul_rn(cx, cx), __fmul_rn(cz, cz)),
                         __fmul_rn(cy, cy));
    __syncthreads();

    int count = 0;
    unsigned lmask = (1u << lane) - 1u;
    int* myidx = s_idx + wid * K;
    for (int base = 0; base < N; base += 64) {
        int n0 = base + lane;
        int n1 = base + 32 + lane;
        // stride-3 word addresses: conflict-free (gcd(3,32)=1)
        float x0 = sxyz[n0 * 3 + 0], y0 = sxyz[n0 * 3 + 1], z0 = sxyz[n0 * 3 + 2];
        float x1 = sxyz[n1 * 3 + 0], y1 = sxyz[n1 * 3 + 1], z1 = sxyz[n1 * 3 + 2];

        float xx0  = __fadd_rn(__fadd_rn(__fmul_rn(x0, x0), __fmul_rn(z0, z0)),
                               __fmul_rn(y0, y0));
        float dot0 = __fmaf_rn(cz, z0, __fmaf_rn(cy, y0, __fmul_rn(cx, x0)));
        float d20  = __fsub_rn(__fadd_rn(cc, xx0), __fmul_rn(2.0f, dot0));
        float xx1  = __fadd_rn(__fadd_rn(__fmul_rn(x1, x1), __fmul_rn(z1, z1)),
                               __fmul_rn(y1, y1));
        float dot1 = __fmaf_rn(cz, z1, __fmaf_rn(cy, y1, __fmul_rn(cx, x1)));
        float d21  = __fsub_rn(__fadd_rn(cc, xx1), __fmul_rn(2.0f, dot1));

        bool in0 = d20 < R2;
        bool in1 = d21 < R2;
        unsigned m0 = __ballot_sync(0xffffffffu, in0);
        unsigned m1 = __ballot_sync(0xffffffffu, in1);
        int c0 = __popc(m0);
        int pos0 = count + __popc(m0 & lmask);
        int pos1 = count + c0 + __popc(m1 & lmask);
        if (in0 && pos0 < K) myidx[pos0] = n0;
        if (in1 && pos1 < K) myidx[pos1] = n1;
        count += c0 + __popc(m1);
        if (count >= K) break;
    }
    if (count > K) count = K;
    __syncwarp();

    int first = (count == 0) ? 0 : myidx[0];
    for (int k = count + lane; k < K; k += 32) myidx[k] = first;
    __syncwarp();

    int*   gidx = g_idx + ((size_t)b * P + p) * K;
    size_t obase = (((size_t)b * OUTC) * P + p) * K;
    #pragma unroll
    for (int t = 0; t < 2; t++) {
        int k = lane + t * 32;
        int n = myidx[k];
        gidx[k] = n;
        float gx = __fdiv_rn(__fsub_rn(sxyz[n * 3 + 0], cx), 0.3f);
        float gy = __fdiv_rn(__fsub_rn(sxyz[n * 3 + 1], cy), 0.3f);
        float gz = __fdiv_rn(__fsub_rn(sxyz[n * 3 + 2], cz), 0.3f);
        out[obase + 0 * (size_t)P * K + k] = gx;
        out[obase + 1 * (size_t)P * K + k] = gy;
        out[obase + 2 * (size_t)P * K + k] = gz;
    }
}

// ---------------------------------------------------------------------------
// Kernel 2: feature grouping, 4 channels per block, 1024 threads.
// Interleaved float4 smem image of 4 feature rows; one LDS.128 per gathered
// point serves 4 output channels. Output stores use streaming hint (never
// re-read -> don't churn L2).
// ---------------------------------------------------------------------------
__global__ __launch_bounds__(1024, 1) void group_feat_kernel(
    const float* __restrict__ feat,   // [B, C, N]
    float* __restrict__ out)          // [B, OUTC, P, K]
{
    extern __shared__ float4 srow[];  // [N] = 128 KB

    int b  = blockIdx.x >> 6;            // / (C/CPB)
    int cq = blockIdx.x & 63;            // channel quad
    int c0 = cq * CPB;

    const float* r0 = feat + (((size_t)b * C + c0 + 0) * N);
    const float* r1 = feat + (((size_t)b * C + c0 + 1) * N);
    const float* r2 = feat + (((size_t)b * C + c0 + 2) * N);
    const float* r3 = feat + (((size_t)b * C + c0 + 3) * N);

    #pragma unroll
    for (int n = threadIdx.x; n < N; n += 1024) {
        float4 v;
        v.x = r0[n]; v.y = r1[n]; v.z = r2[n]; v.w = r3[n];
        srow[n] = v;   // conflict-free STS.128 (consecutive n)
    }
    __syncthreads();

    const int4* idx4 = (const int4*)g_idx + (size_t)b * (P * K / 4);
    size_t ob = ((size_t)b * OUTC + 3 + c0) * P * K;
    float4* d0 = (float4*)(out + ob + 0 * (size_t)P * K);
    float4* d1 = (float4*)(out + ob + 1 * (size_t)P * K);
    float4* d2 = (float4*)(out + ob + 2 * (size_t)P * K);
    float4* d3 = (float4*)(out + ob + 3 * (size_t)P * K);

    #pragma unroll 4
    for (int i = threadIdx.x; i < P * K / 4; i += 1024) {
        int4 v = idx4[i];
        float4 a  = srow[v.x];
        float4 bb = srow[v.y];
        float4 cc = srow[v.z];
        float4 dd = srow[v.w];
        __stcs(&d0[i], make_float4(a.x, bb.x, cc.x, dd.x));
        __stcs(&d1[i], make_float4(a.y, bb.y, cc.y, dd.y));
        __stcs(&d2[i], make_float4(a.z, bb.z, cc.z, dd.z));
        __stcs(&d3[i], make_float4(a.w, bb.w, cc.w, dd.w));
    }
}

extern "C" void kernel_launch(void* const* d_in, const int* in_sizes, int n_in,
                              void* d_out, int out_size)
{
    (void)in_sizes; (void)n_in; (void)out_size;
    const float* xyz     = (const float*)d_in[0];   // [16, 8192, 3]
    const float* new_xyz = (const float*)d_in[1];   // [16, 1024, 3]
    const float* feat    = (const float*)d_in[2];   // [16, 256, 8192]
    float* out = (float*)d_out;                     // [16, 259, 1024, 64]

    const int bq_smem = 3 * N * sizeof(float) + 32 * K * sizeof(int); // 104 KB
    const int gf_smem = N * sizeof(float4);                           // 128 KB
    cudaFuncSetAttribute(ball_query_kernel,
                         cudaFuncAttributeMaxDynamicSharedMemorySize, bq_smem);
    cudaFuncSetAttribute(group_feat_kernel,
                         cudaFuncAttributeMaxDynamicSharedMemorySize, gf_smem);

    ball_query_kernel<<<(B * P) / 32, 1024, bq_smem>>>(xyz, new_xyz, out);
    group_feat_kernel<<<B * (C / CPB), 1024, gf_smem>>>(feat, out);
}

// round 8
// speedup vs baseline: 1.6417x; 1.0091x over previous
#include <cuda_runtime.h>
#include <stdint.h>

#define B    16
#define N    8192
#define P    1024
#define C    256
#define K    64
#define OUTC (3 + C)   // 259
#define CPB  4         // channels per block in group_feat

// Scratch for ball-query indices: [B, P, K] int32 = 4 MB
__device__ int g_idx[B * P * K];

// ---------------------------------------------------------------------------
// Kernel 1: ball query. 128 blocks (8 per batch), 1024 threads (32 warps),
// 4 centers per warp, scanned sequentially. xyz[b] (96 KB) staged in smem
// once per block; scan processes 128 points per iteration (4 batched
// ballots) to amortize the serial LDS->d2->ballot chain.
// Arithmetic (validated in R4, bit-matches reference):
//   ssq tree : (x^2 + z^2) + y^2, separately-rounded muls
//   dot      : fma(cz,z, fma(cy,y, rn(cx*x)))
//   d2       : (cc + xx) - 2*dot
// Selection: first K ascending indices with d2 < r^2; empty slots filled
// with first found index (0 if none).
// ---------------------------------------------------------------------------
__global__ __launch_bounds__(1024, 1) void ball_query_kernel(
    const float* __restrict__ xyz,      // [B, N, 3]
    const float* __restrict__ new_xyz,  // [B, P, 3]
    float* __restrict__ out)            // [B, OUTC, P, K]
{
    const float R2 = (float)(0.3 * 0.3);

    extern __shared__ float smem[];
    float* sxyz  = smem;                     // [3*N] = 96 KB
    int*   s_idx = (int*)(smem + 3 * N);     // [32][K] = 8 KB (one row/warp)

    int tid  = threadIdx.x;
    int lane = tid & 31;
    int wid  = tid >> 5;                     // 0..31
    int b    = blockIdx.x >> 3;              // 8 blocks per batch
    int pgrp = (blockIdx.x & 7) * 128;       // this block's 128 centers

    // Stage xyz[b] into smem (coalesced float4)
    const float4* src = (const float4*)(xyz + (size_t)b * N * 3);
    #pragma unroll
    for (int i = tid; i < 3 * N / 4; i += 1024)
        ((float4*)sxyz)[i] = src[i];
    __syncthreads();

    unsigned lmask = (1u << lane) - 1u;
    int* myidx = s_idx + wid * K;

    // 4 centers per warp, sequential
    for (int cc_i = 0; cc_i < 4; cc_i++) {
        int p = pgrp + wid * 4 + cc_i;

        const float* ctr = new_xyz + ((size_t)b * P + p) * 3;
        float cx = ctr[0], cy = ctr[1], cz = ctr[2];
        float cc = __fadd_rn(__fadd_rn(__fmul_rn(cx, cx), __fmul_rn(cz, cz)),
                             __fmul_rn(cy, cy));

        int count = 0;
        for (int base = 0; base < N; base += 128) {
            unsigned msk[4];
            int cnt[4];
            #pragma unroll
            for (int g = 0; g < 4; g++) {
                int n = base + g * 32 + lane;
                float x = sxyz[n * 3 + 0];
                float y = sxyz[n * 3 + 1];
                float z = sxyz[n * 3 + 2];
                float xx  = __fadd_rn(__fadd_rn(__fmul_rn(x, x), __fmul_rn(z, z)),
                                      __fmul_rn(y, y));
                float dot = __fmaf_rn(cz, z, __fmaf_rn(cy, y, __fmul_rn(cx, x)));
                float d2  = __fsub_rn(__fadd_rn(cc, xx), __fmul_rn(2.0f, dot));
                msk[g] = __ballot_sync(0xffffffffu, d2 < R2);
                cnt[g] = __popc(msk[g]);
            }
            int run = count;
            #pragma unroll
            for (int g = 0; g < 4; g++) {
                int n = base + g * 32 + lane;
                bool in = (msk[g] >> lane) & 1u;
                int pos = run + __popc(msk[g] & lmask);
                if (in && pos < K) myidx[pos] = n;
                run += cnt[g];
            }
            count = run;
            if (count >= K) break;
        }
        if (count > K) count = K;
        __syncwarp();

        int first = (count == 0) ? 0 : myidx[0];
        for (int k = count + lane; k < K; k += 32) myidx[k] = first;
        __syncwarp();

        int*   gidx = g_idx + ((size_t)b * P + p) * K;
        size_t obase = (((size_t)b * OUTC) * P + p) * K;
        #pragma unroll
        for (int t = 0; t < 2; t++) {
            int k = lane + t * 32;
            int n = myidx[k];
            gidx[k] = n;
            float gx = __fdiv_rn(__fsub_rn(sxyz[n * 3 + 0], cx), 0.3f);
            float gy = __fdiv_rn(__fsub_rn(sxyz[n * 3 + 1], cy), 0.3f);
            float gz = __fdiv_rn(__fsub_rn(sxyz[n * 3 + 2], cz), 0.3f);
            out[obase + 0 * (size_t)P * K + k] = gx;
            out[obase + 1 * (size_t)P * K + k] = gy;
            out[obase + 2 * (size_t)P * K + k] = gz;
        }
        __syncwarp();
    }
}

// ---------------------------------------------------------------------------
// Kernel 2: feature grouping, 4 channels per block, 1024 threads.
// Interleaved float4 smem image of 4 feature rows; one LDS.128 per gathered
// point serves 4 output channels. Streaming stores (output never re-read).
// ---------------------------------------------------------------------------
__global__ __launch_bounds__(1024, 1) void group_feat_kernel(
    const float* __restrict__ feat,   // [B, C, N]
    float* __restrict__ out)          // [B, OUTC, P, K]
{
    extern __shared__ float4 srow[];  // [N] = 128 KB

    int b  = blockIdx.x >> 6;            // / (C/CPB)
    int cq = blockIdx.x & 63;            // channel quad
    int c0 = cq * CPB;

    const float* r0 = feat + (((size_t)b * C + c0 + 0) * N);
    const float* r1 = feat + (((size_t)b * C + c0 + 1) * N);
    const float* r2 = feat + (((size_t)b * C + c0 + 2) * N);
    const float* r3 = feat + (((size_t)b * C + c0 + 3) * N);

    #pragma unroll
    for (int n = threadIdx.x; n < N; n += 1024) {
        float4 v;
        v.x = r0[n]; v.y = r1[n]; v.z = r2[n]; v.w = r3[n];
        srow[n] = v;   // conflict-free STS.128 (consecutive n)
    }
    __syncthreads();

    const int4* idx4 = (const int4*)g_idx + (size_t)b * (P * K / 4);
    size_t ob = ((size_t)b * OUTC + 3 + c0) * P * K;
    float4* d0 = (float4*)(out + ob + 0 * (size_t)P * K);
    float4* d1 = (float4*)(out + ob + 1 * (size_t)P * K);
    float4* d2 = (float4*)(out + ob + 2 * (size_t)P * K);
    float4* d3 = (float4*)(out + ob + 3 * (size_t)P * K);

    #pragma unroll 4
    for (int i = threadIdx.x; i < P * K / 4; i += 1024) {
        int4 v = idx4[i];
        float4 a  = srow[v.x];
        float4 bb = srow[v.y];
        float4 cc = srow[v.z];
        float4 dd = srow[v.w];
        __stcs(&d0[i], make_float4(a.x, bb.x, cc.x, dd.x));
        __stcs(&d1[i], make_float4(a.y, bb.y, cc.y, dd.y));
        __stcs(&d2[i], make_float4(a.z, bb.z, cc.z, dd.z));
        __stcs(&d3[i], make_float4(a.w, bb.w, cc.w, dd.w));
    }
}

extern "C" void kernel_launch(void* const* d_in, const int* in_sizes, int n_in,
                              void* d_out, int out_size)
{
    (void)in_sizes; (void)n_in; (void)out_size;
    const float* xyz     = (const float*)d_in[0];   // [16, 8192, 3]
    const float* new_xyz = (const float*)d_in[1];   // [16, 1024, 3]
    const float* feat    = (const float*)d_in[2];   // [16, 256, 8192]
    float* out = (float*)d_out;                     // [16, 259, 1024, 64]

    const int bq_smem = 3 * N * sizeof(float) + 32 * K * sizeof(int); // 104 KB
    const int gf_smem = N * sizeof(float4);                           // 128 KB
    cudaFuncSetAttribute(ball_query_kernel,
                         cudaFuncAttributeMaxDynamicSharedMemorySize, bq_smem);
    cudaFuncSetAttribute(group_feat_kernel,
                         cudaFuncAttributeMaxDynamicSharedMemorySize, gf_smem);

    ball_query_kernel<<<128, 1024, bq_smem>>>(xyz, new_xyz, out);
    group_feat_kernel<<<B * (C / CPB), 1024, gf_smem>>>(feat, out);
}